// round 6
// baseline (speedup 1.0000x reference)
#include <cuda_runtime.h>
#include <cuda_fp16.h>

// Problem constants (dataset is fixed: 50000 nodes, 800000 edges, 64 feats)
#define MAX_NODES 50048
#define MAX_EDGES 800000
#define SCAN_BLK  1024
#define MAX_SCAN_BLOCKS 64   // ceil(50000/1024) = 49
#define N_FIXED   50000

// Scratch (allocation-free rule: __device__ globals). Zero-init at load;
// g_count is re-zeroed by k_gather each launch so replays stay correct.
__device__ int    g_count[MAX_NODES];
__device__ int    g_offset[MAX_NODES + 1];
__device__ int    g_cursor[MAX_NODES];
__device__ int    g_srow[MAX_EDGES];
__device__ int    g_blocksum[MAX_SCAN_BLOCKS];
__device__ __half g_xh[N_FIXED * 64];          // fp16 staging copy of x (6.4 MB)

// x (f32) -> g_xh (fp16). float4 read, 8B write, fully coalesced.
__global__ void k_convert(const float* __restrict__ x, int n16) {
    int i = blockIdx.x * blockDim.x + threadIdx.x;
    if (i < n16) {
        float4 v = reinterpret_cast<const float4*>(x)[i];
        __half2 h0 = __floats2half2_rn(v.x, v.y);
        __half2 h1 = __floats2half2_rn(v.z, v.w);
        uint2 u;
        u.x = *reinterpret_cast<unsigned*>(&h0);
        u.y = *reinterpret_cast<unsigned*>(&h1);
        reinterpret_cast<uint2*>(g_xh)[i] = u;
    }
}

// Histogram of destinations. int4-vectorized edge reads (E % 4 == 0).
__global__ void k_hist(const int* __restrict__ col, int E4) {
    int i = blockIdx.x * blockDim.x + threadIdx.x;
    if (i < E4) {
        int4 c = reinterpret_cast<const int4*>(col)[i];
        atomicAdd(&g_count[c.x], 1);
        atomicAdd(&g_count[c.y], 1);
        atomicAdd(&g_count[c.z], 1);
        atomicAdd(&g_count[c.w], 1);
    }
}

// Coalesced block reduce of g_count -> g_blocksum
__global__ void k_scanA(int n) {
    __shared__ int s_warp[32];
    int i = blockIdx.x * SCAN_BLK + threadIdx.x;
    int v = (i < n) ? g_count[i] : 0;
    #pragma unroll
    for (int o = 16; o > 0; o >>= 1) v += __shfl_down_sync(0xffffffffu, v, o);
    int wid = threadIdx.x >> 5, lane = threadIdx.x & 31;
    if (lane == 0) s_warp[wid] = v;
    __syncthreads();
    if (wid == 0) {
        int s = s_warp[lane];
        #pragma unroll
        for (int o = 16; o > 0; o >>= 1) s += __shfl_down_sync(0xffffffffu, s, o);
        if (lane == 0) g_blocksum[blockIdx.x] = s;
    }
}

// Each block: redundant global base from the 49 blocksums, then shuffle-based
// exclusive tile scan -> g_offset / g_cursor. All accesses coalesced.
__global__ void k_scanC(int n, int nblocks) {
    __shared__ int s_sums[MAX_SCAN_BLOCKS];
    __shared__ int s_warp[32];
    int t = threadIdx.x;
    int wid = t >> 5, lane = t & 31;
    int i = blockIdx.x * SCAN_BLK + t;

    if (t < MAX_SCAN_BLOCKS) s_sums[t] = (t < nblocks) ? g_blocksum[t] : 0;
    int v = (i < n) ? g_count[i] : 0;
    __syncthreads();

    int base = 0;
    for (int j = 0; j < blockIdx.x; j++) base += s_sums[j];   // broadcast LDS

    int incl = v;
    #pragma unroll
    for (int o = 1; o < 32; o <<= 1) {
        int u = __shfl_up_sync(0xffffffffu, incl, o);
        if (lane >= o) incl += u;
    }
    if (lane == 31) s_warp[wid] = incl;
    __syncthreads();
    int wpre = 0;
    for (int j = 0; j < wid; j++) wpre += s_warp[j];           // broadcast LDS

    int excl = base + wpre + incl - v;
    if (i < n) {
        g_offset[i] = excl;
        g_cursor[i] = excl;
        if (i == n - 1) g_offset[n] = excl + v;   // total == E
    }
}

// Counting sort of edge sources by destination. int4-vectorized reads.
__global__ void k_scatter(const int* __restrict__ row, const int* __restrict__ col, int E4) {
    int i = blockIdx.x * blockDim.x + threadIdx.x;
    if (i < E4) {
        int4 r = reinterpret_cast<const int4*>(row)[i];
        int4 c = reinterpret_cast<const int4*>(col)[i];
        g_srow[atomicAdd(&g_cursor[c.x], 1)] = r.x;
        g_srow[atomicAdd(&g_cursor[c.y], 1)] = r.y;
        g_srow[atomicAdd(&g_cursor[c.z], 1)] = r.z;
        g_srow[atomicAdd(&g_cursor[c.w], 1)] = r.w;
    }
}

// HALF-WARP per destination node; lane handles feats [4*hw, 4*hw+3].
// One edge = 16 lanes x 8B = one 128B line of g_xh. fp32 accumulation.
// Also re-zeroes g_count for the next graph replay (free bandwidth).
__global__ void k_gather(float* __restrict__ out, int n) {
    int gtid = blockIdx.x * blockDim.x + threadIdx.x;

    // restore g_count = 0 for next launch (12512 int4 stores, trivial)
    if (gtid < MAX_NODES / 4)
        reinterpret_cast<int4*>(g_count)[gtid] = make_int4(0, 0, 0, 0);

    int node = gtid >> 4;              // half-warp group id
    int hw   = threadIdx.x & 15;       // lane within group
    if (node >= n) return;
    int start = g_offset[node];
    int end   = g_offset[node + 1];

    float4 a0 = make_float4(0.f, 0.f, 0.f, 0.f);
    float4 a1 = make_float4(0.f, 0.f, 0.f, 0.f);
    float4 a2 = make_float4(0.f, 0.f, 0.f, 0.f);
    float4 a3 = make_float4(0.f, 0.f, 0.f, 0.f);

    int i = start;
    for (; i + 4 <= end; i += 4) {
        int r0 = g_srow[i];
        int r1 = g_srow[i + 1];
        int r2 = g_srow[i + 2];
        int r3 = g_srow[i + 3];
        uint2 u0 = reinterpret_cast<const uint2*>(g_xh + ((size_t)r0 << 6))[hw];
        uint2 u1 = reinterpret_cast<const uint2*>(g_xh + ((size_t)r1 << 6))[hw];
        uint2 u2 = reinterpret_cast<const uint2*>(g_xh + ((size_t)r2 << 6))[hw];
        uint2 u3 = reinterpret_cast<const uint2*>(g_xh + ((size_t)r3 << 6))[hw];
        {
            float2 lo = __half22float2(*reinterpret_cast<__half2*>(&u0.x));
            float2 hi = __half22float2(*reinterpret_cast<__half2*>(&u0.y));
            a0.x += lo.x; a0.y += lo.y; a0.z += hi.x; a0.w += hi.y;
        }
        {
            float2 lo = __half22float2(*reinterpret_cast<__half2*>(&u1.x));
            float2 hi = __half22float2(*reinterpret_cast<__half2*>(&u1.y));
            a1.x += lo.x; a1.y += lo.y; a1.z += hi.x; a1.w += hi.y;
        }
        {
            float2 lo = __half22float2(*reinterpret_cast<__half2*>(&u2.x));
            float2 hi = __half22float2(*reinterpret_cast<__half2*>(&u2.y));
            a2.x += lo.x; a2.y += lo.y; a2.z += hi.x; a2.w += hi.y;
        }
        {
            float2 lo = __half22float2(*reinterpret_cast<__half2*>(&u3.x));
            float2 hi = __half22float2(*reinterpret_cast<__half2*>(&u3.y));
            a3.x += lo.x; a3.y += lo.y; a3.z += hi.x; a3.w += hi.y;
        }
    }
    for (; i < end; i++) {
        int r0 = g_srow[i];
        uint2 u0 = reinterpret_cast<const uint2*>(g_xh + ((size_t)r0 << 6))[hw];
        float2 lo = __half22float2(*reinterpret_cast<__half2*>(&u0.x));
        float2 hi = __half22float2(*reinterpret_cast<__half2*>(&u0.y));
        a0.x += lo.x; a0.y += lo.y; a0.z += hi.x; a0.w += hi.y;
    }

    int deg = end - start;
    float inv = 1.0f / (float)(deg > 0 ? deg : 1);
    float4 o;
    o.x = (a0.x + a1.x + a2.x + a3.x) * inv;
    o.y = (a0.y + a1.y + a2.y + a3.y) * inv;
    o.z = (a0.z + a1.z + a2.z + a3.z) * inv;
    o.w = (a0.w + a1.w + a2.w + a3.w) * inv;
    *reinterpret_cast<float4*>(out + ((size_t)node << 6) + (hw << 2)) = o;
}

extern "C" void kernel_launch(void* const* d_in, const int* in_sizes, int n_in,
                              void* d_out, int out_size) {
    const float* x    = (const float*)d_in[0];
    const int*   edge = (const int*)d_in[1];
    float*       out  = (float*)d_out;

    const int n   = in_sizes[0] / 64;   // 50000
    const int E   = in_sizes[1] / 2;    // 800000
    const int E4  = E / 4;              // 200000 (E % 4 == 0)
    const int n16 = n * 16;             // float4 count = n*64/4 = 800000  (BUGFIX)
    const int* row = edge;              // edge_index[0, :]
    const int* col = edge + E;          // edge_index[1, :]

    const int nb_scan = (n + SCAN_BLK - 1) / SCAN_BLK;   // 49

    k_convert<<<(n16 + 255) / 256, 256>>>(x, n16);
    k_hist   <<<(E4 + 255) / 256, 256>>>(col, E4);
    k_scanA  <<<nb_scan, SCAN_BLK>>>(n);
    k_scanC  <<<nb_scan, SCAN_BLK>>>(n, nb_scan);
    k_scatter<<<(E4 + 255) / 256, 256>>>(row, col, E4);
    // 16 half-warp groups per 256-thread block, one group per node
    k_gather <<<(n + 15) / 16, 256>>>(out, n);
}

// round 7
// speedup vs baseline: 1.0441x; 1.0441x over previous
#include <cuda_runtime.h>
#include <cuda_fp16.h>

// Problem constants (dataset is fixed: 50000 nodes, 800000 edges, 64 feats)
#define MAX_NODES 50048
#define MAX_EDGES 800000
#define SCAN_BLK  1024
#define MAX_SCAN_BLOCKS 64   // ceil(50000/1024) = 49
#define N_FIXED   50000

// Scratch (allocation-free rule: __device__ globals). Zero-init at load;
// g_count / g_ready are re-zeroed by k_gather so graph replays stay correct.
__device__ int    g_count[MAX_NODES];
__device__ int    g_offset[MAX_NODES + 1];
__device__ int    g_cursor[MAX_NODES];
__device__ int    g_srow[MAX_EDGES];
__device__ int    g_blocksum[MAX_SCAN_BLOCKS];
__device__ int    g_ready;                     // published-blocksum counter
__device__ __half g_xh[N_FIXED * 64];          // fp16 staging copy of x (6.4 MB)

// Fused: blocks [0, cvtBlocks) convert x->fp16; rest histogram destinations.
__global__ void k_prep(const float* __restrict__ x, const int* __restrict__ col,
                       int n16, int E4, int cvtBlocks) {
    if (blockIdx.x < cvtBlocks) {
        int i = blockIdx.x * blockDim.x + threadIdx.x;
        if (i < n16) {
            float4 v = reinterpret_cast<const float4*>(x)[i];
            __half2 h0 = __floats2half2_rn(v.x, v.y);
            __half2 h1 = __floats2half2_rn(v.z, v.w);
            uint2 u;
            u.x = *reinterpret_cast<unsigned*>(&h0);
            u.y = *reinterpret_cast<unsigned*>(&h1);
            reinterpret_cast<uint2*>(g_xh)[i] = u;
        }
    } else {
        int i = (blockIdx.x - cvtBlocks) * blockDim.x + threadIdx.x;
        if (i < E4) {
            int4 c = reinterpret_cast<const int4*>(col)[i];
            atomicAdd(&g_count[c.x], 1);
            atomicAdd(&g_count[c.y], 1);
            atomicAdd(&g_count[c.z], 1);
            atomicAdd(&g_count[c.w], 1);
        }
    }
}

// Single-pass scan: 49 co-resident blocks. Each block scans its tile,
// publishes the tile total, spins for all totals, adds its base.
__global__ void k_scan(int n, int nblocks) {
    __shared__ int s_warp[32];      // warp inclusive-scan totals
    __shared__ int s_wpre[32];      // exclusive warp prefixes
    __shared__ int s_sums[MAX_SCAN_BLOCKS];
    int t = threadIdx.x;
    int wid = t >> 5, lane = t & 31;
    int b = blockIdx.x;
    int i = b * SCAN_BLK + t;
    int v = (i < n) ? g_count[i] : 0;

    // warp inclusive scan
    int incl = v;
    #pragma unroll
    for (int o = 1; o < 32; o <<= 1) {
        int u = __shfl_up_sync(0xffffffffu, incl, o);
        if (lane >= o) incl += u;
    }
    if (lane == 31) s_warp[wid] = incl;
    __syncthreads();

    // warp 0: scan the 32 warp totals -> exclusive prefixes + block total
    if (wid == 0) {
        int w = s_warp[lane];
        int winc = w;
        #pragma unroll
        for (int o = 1; o < 32; o <<= 1) {
            int u = __shfl_up_sync(0xffffffffu, winc, o);
            if (lane >= o) winc += u;
        }
        s_wpre[lane] = winc - w;
        if (lane == 31) {
            g_blocksum[b] = winc;          // block total
            __threadfence();
            atomicAdd(&g_ready, 1);        // publish
        }
    }
    __syncthreads();

    // wait for all 49 block totals (all blocks co-resident -> no deadlock)
    if (t == 0) {
        while (atomicAdd(&g_ready, 0) < nblocks) { __nanosleep(64); }
    }
    __syncthreads();
    if (t < MAX_SCAN_BLOCKS) s_sums[t] = (t < nblocks) ? __ldcg(&g_blocksum[t]) : 0;
    __syncthreads();

    int base = 0;
    for (int j = 0; j < b; j++) base += s_sums[j];   // broadcast LDS

    int excl = base + s_wpre[wid] + incl - v;
    if (i < n) {
        g_offset[i] = excl;
        g_cursor[i] = excl;
        if (i == n - 1) g_offset[n] = excl + v;      // total == E
    }
}

// Counting sort of edge sources by destination. 8 edges/thread for MLP.
__global__ void k_scatter(const int* __restrict__ row, const int* __restrict__ col, int E4) {
    int i = (blockIdx.x * blockDim.x + threadIdx.x) * 2;
    if (i + 1 < E4) {
        int4 r0 = reinterpret_cast<const int4*>(row)[i];
        int4 r1 = reinterpret_cast<const int4*>(row)[i + 1];
        int4 c0 = reinterpret_cast<const int4*>(col)[i];
        int4 c1 = reinterpret_cast<const int4*>(col)[i + 1];
        g_srow[atomicAdd(&g_cursor[c0.x], 1)] = r0.x;
        g_srow[atomicAdd(&g_cursor[c0.y], 1)] = r0.y;
        g_srow[atomicAdd(&g_cursor[c0.z], 1)] = r0.z;
        g_srow[atomicAdd(&g_cursor[c0.w], 1)] = r0.w;
        g_srow[atomicAdd(&g_cursor[c1.x], 1)] = r1.x;
        g_srow[atomicAdd(&g_cursor[c1.y], 1)] = r1.y;
        g_srow[atomicAdd(&g_cursor[c1.z], 1)] = r1.z;
        g_srow[atomicAdd(&g_cursor[c1.w], 1)] = r1.w;
    } else if (i < E4) {
        int4 r0 = reinterpret_cast<const int4*>(row)[i];
        int4 c0 = reinterpret_cast<const int4*>(col)[i];
        g_srow[atomicAdd(&g_cursor[c0.x], 1)] = r0.x;
        g_srow[atomicAdd(&g_cursor[c0.y], 1)] = r0.y;
        g_srow[atomicAdd(&g_cursor[c0.z], 1)] = r0.z;
        g_srow[atomicAdd(&g_cursor[c0.w], 1)] = r0.w;
    }
}

// HALF-WARP per destination node; lane handles feats [4*hw, 4*hw+3].
// One edge = 16 lanes x 8B = one 128B line of g_xh. fp32 accumulation.
// Also resets g_count / g_ready for the next graph replay.
__global__ void k_gather(float* __restrict__ out, int n) {
    int gtid = blockIdx.x * blockDim.x + threadIdx.x;

    if (gtid < MAX_NODES / 4)
        reinterpret_cast<int4*>(g_count)[gtid] = make_int4(0, 0, 0, 0);
    if (gtid == 0) g_ready = 0;

    int node = gtid >> 4;              // half-warp group id
    int hw   = threadIdx.x & 15;       // lane within group
    if (node >= n) return;
    int start = g_offset[node];
    int end   = g_offset[node + 1];

    float4 a0 = make_float4(0.f, 0.f, 0.f, 0.f);
    float4 a1 = make_float4(0.f, 0.f, 0.f, 0.f);
    float4 a2 = make_float4(0.f, 0.f, 0.f, 0.f);
    float4 a3 = make_float4(0.f, 0.f, 0.f, 0.f);

    int i = start;
    for (; i + 4 <= end; i += 4) {
        int r0 = g_srow[i];
        int r1 = g_srow[i + 1];
        int r2 = g_srow[i + 2];
        int r3 = g_srow[i + 3];
        uint2 u0 = reinterpret_cast<const uint2*>(g_xh + ((size_t)r0 << 6))[hw];
        uint2 u1 = reinterpret_cast<const uint2*>(g_xh + ((size_t)r1 << 6))[hw];
        uint2 u2 = reinterpret_cast<const uint2*>(g_xh + ((size_t)r2 << 6))[hw];
        uint2 u3 = reinterpret_cast<const uint2*>(g_xh + ((size_t)r3 << 6))[hw];
        {
            float2 lo = __half22float2(*reinterpret_cast<__half2*>(&u0.x));
            float2 hi = __half22float2(*reinterpret_cast<__half2*>(&u0.y));
            a0.x += lo.x; a0.y += lo.y; a0.z += hi.x; a0.w += hi.y;
        }
        {
            float2 lo = __half22float2(*reinterpret_cast<__half2*>(&u1.x));
            float2 hi = __half22float2(*reinterpret_cast<__half2*>(&u1.y));
            a1.x += lo.x; a1.y += lo.y; a1.z += hi.x; a1.w += hi.y;
        }
        {
            float2 lo = __half22float2(*reinterpret_cast<__half2*>(&u2.x));
            float2 hi = __half22float2(*reinterpret_cast<__half2*>(&u2.y));
            a2.x += lo.x; a2.y += lo.y; a2.z += hi.x; a2.w += hi.y;
        }
        {
            float2 lo = __half22float2(*reinterpret_cast<__half2*>(&u3.x));
            float2 hi = __half22float2(*reinterpret_cast<__half2*>(&u3.y));
            a3.x += lo.x; a3.y += lo.y; a3.z += hi.x; a3.w += hi.y;
        }
    }
    for (; i < end; i++) {
        int r0 = g_srow[i];
        uint2 u0 = reinterpret_cast<const uint2*>(g_xh + ((size_t)r0 << 6))[hw];
        float2 lo = __half22float2(*reinterpret_cast<__half2*>(&u0.x));
        float2 hi = __half22float2(*reinterpret_cast<__half2*>(&u0.y));
        a0.x += lo.x; a0.y += lo.y; a0.z += hi.x; a0.w += hi.y;
    }

    int deg = end - start;
    float inv = 1.0f / (float)(deg > 0 ? deg : 1);
    float4 o;
    o.x = (a0.x + a1.x + a2.x + a3.x) * inv;
    o.y = (a0.y + a1.y + a2.y + a3.y) * inv;
    o.z = (a0.z + a1.z + a2.z + a3.z) * inv;
    o.w = (a0.w + a1.w + a2.w + a3.w) * inv;
    *reinterpret_cast<float4*>(out + ((size_t)node << 6) + (hw << 2)) = o;
}

extern "C" void kernel_launch(void* const* d_in, const int* in_sizes, int n_in,
                              void* d_out, int out_size) {
    const float* x    = (const float*)d_in[0];
    const int*   edge = (const int*)d_in[1];
    float*       out  = (float*)d_out;

    const int n   = in_sizes[0] / 64;   // 50000
    const int E   = in_sizes[1] / 2;    // 800000
    const int E4  = E / 4;              // 200000 (E % 4 == 0)
    const int n16 = n * 16;             // float4 count of x = 800000
    const int* row = edge;              // edge_index[0, :]
    const int* col = edge + E;          // edge_index[1, :]

    const int nb_scan   = (n + SCAN_BLK - 1) / SCAN_BLK;       // 49
    const int cvtBlocks = (n16 + 255) / 256;                   // 3125
    const int histBlocks = (E4 + 255) / 256;                   // 782
    const int scatBlocks = (E4 / 2 + 255) / 256;               // 391

    k_prep   <<<cvtBlocks + histBlocks, 256>>>(x, col, n16, E4, cvtBlocks);
    k_scan   <<<nb_scan, SCAN_BLK>>>(n, nb_scan);
    k_scatter<<<scatBlocks, 256>>>(row, col, E4);
    k_gather <<<(n + 15) / 16, 256>>>(out, n);
}